// round 1
// baseline (speedup 1.0000x reference)
#include <cuda_runtime.h>
#include <cuda_bf16.h>

// ForgetMult: h_t = f_t * x_t + (1 - f_t) * h_{t-1}, scan over time axis.
// Layout: [seq, nch] with nch = BATCH*HIDDEN contiguous. One thread per
// channel; serial loop over time with register double-buffered prefetch.
// Purely HBM-bound: 402 MB total traffic -> ~57 us floor on GB300.

#define FM_UNROLL 8
#define FM_BLOCK 128

__global__ __launch_bounds__(FM_BLOCK) void ForgetMult_16647293240039_kernel(
    const float* __restrict__ f,
    const float* __restrict__ x,
    const float* __restrict__ h0,
    float* __restrict__ out,
    int seq, int nch)
{
    int c = blockIdx.x * FM_BLOCK + threadIdx.x;
    if (c >= nch) return;

    float h = h0[c];
    const float* fp = f + c;
    const float* xp = x + c;
    float*       op = out + c;

    float fb[2][FM_UNROLL];
    float xb[2][FM_UNROLL];

    const int nfull = seq / FM_UNROLL;

    // Prologue: load chunk 0 into buffer 0.
    if (nfull > 0) {
#pragma unroll
        for (int j = 0; j < FM_UNROLL; j++) {
            fb[0][j] = __ldcs(fp + j * nch);
            xb[0][j] = __ldcs(xp + j * nch);
        }
    }

    int buf = 0;
    int base = 0;                       // element offset of current chunk row 0
    const int chunk_stride = FM_UNROLL * nch;

    for (int blk = 0; blk < nfull; blk++) {
        const int nb = buf ^ 1;
        // Prefetch next chunk while current chunk's loads complete / compute runs.
        if (blk + 1 < nfull) {
            const int nbase = base + chunk_stride;
#pragma unroll
            for (int j = 0; j < FM_UNROLL; j++) {
                fb[nb][j] = __ldcs(fp + nbase + j * nch);
                xb[nb][j] = __ldcs(xp + nbase + j * nch);
            }
        }
        // Serial recurrence over this chunk.
#pragma unroll
        for (int j = 0; j < FM_UNROLL; j++) {
            const float ft = fb[buf][j];
            const float fx = ft * xb[buf][j];
            h = fmaf(1.0f - ft, h, fx);
            __stcs(op + base + j * nch, h);
        }
        base += chunk_stride;
        buf = nb;
    }

    // Tail (seq not divisible by FM_UNROLL).
    for (int t = nfull * FM_UNROLL; t < seq; t++) {
        const float ft = __ldcs(fp + t * nch);
        const float fx = ft * __ldcs(xp + t * nch);
        h = fmaf(1.0f - ft, h, fx);
        __stcs(op + t * nch, h);
    }
}

extern "C" void kernel_launch(void* const* d_in, const int* in_sizes, int n_in,
                              void* d_out, int out_size)
{
    const float* f  = (const float*)d_in[0];
    const float* x  = (const float*)d_in[1];
    const float* h0 = (const float*)d_in[2];
    float* out      = (float*)d_out;

    const int nch = in_sizes[2];           // BATCH * HIDDEN (16384)
    const int seq = in_sizes[0] / nch;     // 2048

    const int grid = (nch + FM_BLOCK - 1) / FM_BLOCK;
    ForgetMult_16647293240039_kernel<<<grid, FM_BLOCK>>>(f, x, h0, out, seq, nch);
}

// round 3
// speedup vs baseline: 3.9576x; 3.9576x over previous
#include <cuda_runtime.h>

// ForgetMult: h_t = f_t*x_t + (1-f_t)*h_{t-1} over seq axis.
// Chunked parallel scan: K1 per-chunk summaries (a = prod(1-f), b = local scan),
// K2 tiny serial scan over chunk summaries -> chunk-start states,
// K3 re-stream f,x and run exact recurrence from chunk-start state.
// Parallelism = nchunks * channels -> ~50 warps/SM, BW-bound (~690 MB DRAM).

#define FM_SEQ     2048
#define FM_NCH     16384
#define FM_NCHUNKS 64
#define FM_L       (FM_SEQ / FM_NCHUNKS)   // 32 timesteps per chunk
#define FM_NG      (FM_NCH / 4)            // 4096 float4 channel-groups
#define FM_TPB     128
#define FM_NTILES  (FM_NG / FM_TPB)        // 32 tiles of 128 groups

// Static scratch (allocation-free rule: __device__ globals).
__device__ float4 g_a[FM_NCHUNKS][FM_NG];       // 4 MB
__device__ float4 g_b[FM_NCHUNKS][FM_NG];       // 4 MB
__device__ float4 g_hstart[FM_NCHUNKS][FM_NG];  // 4 MB

// ---------------- K1: per-chunk summaries ----------------
__global__ __launch_bounds__(FM_TPB) void fm_k1(
    const float4* __restrict__ f, const float4* __restrict__ x)
{
    const int chunk = blockIdx.y;
    const int g     = blockIdx.x * FM_TPB + threadIdx.x;   // float4 group id
    const float4* fp = f + (size_t)chunk * FM_L * FM_NG + g;
    const float4* xp = x + (size_t)chunk * FM_L * FM_NG + g;

    float4 a = make_float4(1.f, 1.f, 1.f, 1.f);
    float4 b = make_float4(0.f, 0.f, 0.f, 0.f);

#pragma unroll 4
    for (int t = 0; t < FM_L; t++) {
        const float4 ft = __ldcs(fp + (size_t)t * FM_NG);
        const float4 xt = __ldcs(xp + (size_t)t * FM_NG);
        float gx = 1.f - ft.x, gy = 1.f - ft.y, gz = 1.f - ft.z, gw = 1.f - ft.w;
        b.x = fmaf(gx, b.x, ft.x * xt.x);  a.x *= gx;
        b.y = fmaf(gy, b.y, ft.y * xt.y);  a.y *= gy;
        b.z = fmaf(gz, b.z, ft.z * xt.z);  a.z *= gz;
        b.w = fmaf(gw, b.w, ft.w * xt.w);  a.w *= gw;
    }
    g_a[chunk][g] = a;
    g_b[chunk][g] = b;
}

// ---------------- K2: scan chunk summaries -> chunk-start states ----------------
__global__ __launch_bounds__(FM_TPB) void fm_k2(const float4* __restrict__ h0)
{
    const int g = blockIdx.x * FM_TPB + threadIdx.x;  // 0..FM_NG-1
    float4 h = h0[g];
#pragma unroll 8
    for (int i = 0; i < FM_NCHUNKS; i++) {
        g_hstart[i][g] = h;                 // exclusive prefix: state at chunk start
        const float4 a = g_a[i][g];
        const float4 b = g_b[i][g];
        h.x = fmaf(a.x, h.x, b.x);
        h.y = fmaf(a.y, h.y, b.y);
        h.z = fmaf(a.z, h.z, b.z);
        h.w = fmaf(a.w, h.w, b.w);
    }
}

// ---------------- K3: full recurrence per chunk from its start state ----------------
__global__ __launch_bounds__(FM_TPB) void fm_k3(
    const float4* __restrict__ f, const float4* __restrict__ x,
    float4* __restrict__ out)
{
    const int chunk = blockIdx.y;
    const int g     = blockIdx.x * FM_TPB + threadIdx.x;
    const size_t base = (size_t)chunk * FM_L * FM_NG + g;
    const float4* fp = f + base;
    const float4* xp = x + base;
    float4*       op = out + base;

    float4 h = g_hstart[chunk][g];

#pragma unroll 4
    for (int t = 0; t < FM_L; t++) {
        const float4 ft = __ldcs(fp + (size_t)t * FM_NG);
        const float4 xt = __ldcs(xp + (size_t)t * FM_NG);
        h.x = fmaf(1.f - ft.x, h.x, ft.x * xt.x);
        h.y = fmaf(1.f - ft.y, h.y, ft.y * xt.y);
        h.z = fmaf(1.f - ft.z, h.z, ft.z * xt.z);
        h.w = fmaf(1.f - ft.w, h.w, ft.w * xt.w);
        __stcs(op + (size_t)t * FM_NG, h);
    }
}

// ---------------- Fallback: naive per-channel scan (unexpected shapes) ----------------
__global__ void fm_naive(const float* __restrict__ f, const float* __restrict__ x,
                         const float* __restrict__ h0, float* __restrict__ out,
                         int seq, int nch)
{
    int c = blockIdx.x * blockDim.x + threadIdx.x;
    if (c >= nch) return;
    float h = h0[c];
    for (int t = 0; t < seq; t++) {
        const float ft = f[(size_t)t * nch + c];
        h = fmaf(1.f - ft, h, ft * x[(size_t)t * nch + c]);
        out[(size_t)t * nch + c] = h;
    }
}

extern "C" void kernel_launch(void* const* d_in, const int* in_sizes, int n_in,
                              void* d_out, int out_size)
{
    const float* f  = (const float*)d_in[0];
    const float* x  = (const float*)d_in[1];
    const float* h0 = (const float*)d_in[2];
    float* out      = (float*)d_out;

    const int nch = in_sizes[2];
    const int seq = in_sizes[0] / nch;

    if (seq == FM_SEQ && nch == FM_NCH) {
        dim3 grid(FM_NTILES, FM_NCHUNKS);
        fm_k1<<<grid, FM_TPB>>>((const float4*)f, (const float4*)x);
        fm_k2<<<FM_NG / FM_TPB, FM_TPB>>>((const float4*)h0);
        fm_k3<<<grid, FM_TPB>>>((const float4*)f, (const float4*)x, (float4*)out);
    } else {
        int tpb = 128;
        fm_naive<<<(nch + tpb - 1) / tpb, tpb>>>(f, x, h0, out, seq, nch);
    }
}

// round 4
// speedup vs baseline: 5.3277x; 1.3462x over previous
#include <cuda_runtime.h>
#include <cstdint>

// ForgetMult fused single-pass chunked scan with decoupled lookback.
// h_t = f_t*x_t + (1-f_t)*h_{t-1}  ==  h_t = h_{t-1} + f_t*(x_t - h_{t-1})
//
// Block (chunk, tile): cp.async chunk tile of f,x into smem ONCE (64 KB),
// compute chunk summary (a = prod(1-f), b = local scan from 0), publish,
// lookback-compose predecessors to get h_start, then exact recurrence from
// smem -> out. DRAM traffic ~440 MB (vs 714 MB for 3-kernel version).

#define FM_SEQ     2048
#define FM_NCH     16384
#define FM_NG      (FM_NCH / 4)          // 4096 float4 channel-groups
#define FM_L       16                    // timesteps per chunk
#define FM_NCHUNKS (FM_SEQ / FM_L)       // 128
#define FM_TPB     128                   // threads/block == groups per tile
#define FM_NTILES  (FM_NG / FM_TPB)      // 32
#define FM_NBLK    (FM_NCHUNKS * FM_NTILES)  // 4096
#define FM_SMEM    (2 * FM_L * FM_TPB * 16)  // 65536 bytes

// Scratch (allocation-free rule: __device__ globals). ~24 MB + flags.
__device__ float4 g_pa[FM_NCHUNKS][FM_NG];
__device__ float4 g_pb[FM_NCHUNKS][FM_NG];
__device__ float4 g_inc[FM_NCHUNKS][FM_NG];
__device__ int    g_flag[FM_NCHUNKS][FM_NTILES];   // 0=none, 1=partial, 2=inclusive

__global__ void fm_init_flags()
{
    int i = blockIdx.x * blockDim.x + threadIdx.x;
    if (i < FM_NCHUNKS * FM_NTILES) ((int*)g_flag)[i] = 0;
}

__device__ __forceinline__ void cp_async16(void* s, const void* g)
{
    uint32_t sa = (uint32_t)__cvta_generic_to_shared(s);
    asm volatile("cp.async.cg.shared.global [%0], [%1], 16;\n" :: "r"(sa), "l"(g));
}

__global__ __launch_bounds__(FM_TPB) void fm_fused(
    const float4* __restrict__ f, const float4* __restrict__ x,
    const float4* __restrict__ h0, float4* __restrict__ out)
{
    // chunk-major bids: lookback waits only on lower block IDs (deadlock-free).
    const int chunk = blockIdx.x / FM_NTILES;
    const int tile  = blockIdx.x % FM_NTILES;
    const int tid   = threadIdx.x;
    const int g     = tile * FM_TPB + tid;

    extern __shared__ float4 s_buf[];
    float4* sf = s_buf;                    // [FM_L][FM_TPB]
    float4* sx = s_buf + FM_L * FM_TPB;    // [FM_L][FM_TPB]
    __shared__ int s_state;

    const size_t base = (size_t)chunk * FM_L * FM_NG + g;

    // ---- Load whole chunk tile into smem (deep async pipeline, L2-only) ----
#pragma unroll
    for (int t = 0; t < FM_L; t++) {
        cp_async16(&sf[t * FM_TPB + tid], f + base + (size_t)t * FM_NG);
        cp_async16(&sx[t * FM_TPB + tid], x + base + (size_t)t * FM_NG);
    }
    asm volatile("cp.async.commit_group;\n" ::: "memory");
    asm volatile("cp.async.wait_group 0;\n" ::: "memory");
    __syncthreads();

    // ---- Pass A: chunk summary per channel: a = prod(1-f), b = scan from 0 ----
    float4 a = make_float4(1.f, 1.f, 1.f, 1.f);
    float4 b = make_float4(0.f, 0.f, 0.f, 0.f);
#pragma unroll
    for (int t = 0; t < FM_L; t++) {
        const float4 ft = sf[t * FM_TPB + tid];
        const float4 xt = sx[t * FM_TPB + tid];
        b.x = fmaf(ft.x, xt.x - b.x, b.x);  a.x *= (1.f - ft.x);
        b.y = fmaf(ft.y, xt.y - b.y, b.y);  a.y *= (1.f - ft.y);
        b.z = fmaf(ft.z, xt.z - b.z, b.z);  a.z *= (1.f - ft.z);
        b.w = fmaf(ft.w, xt.w - b.w, b.w);  a.w *= (1.f - ft.w);
    }

    // ---- Resolve h_start ----
    float4 hstart;
    if (chunk == 0) {
        hstart = h0[g];
    } else {
        // Publish partial summary, then flag=1.
        g_pa[chunk][g] = a;
        g_pb[chunk][g] = b;
        __threadfence();
        __syncthreads();
        if (tid == 0) atomicExch(&g_flag[chunk][tile], 1);

        // Decoupled lookback: h_start(chunk) = B + A * h_end(j), walk j down.
        float4 A = make_float4(1.f, 1.f, 1.f, 1.f);
        float4 B = make_float4(0.f, 0.f, 0.f, 0.f);
        int j = chunk - 1;
        for (;;) {
            if (tid == 0) {
                int s;
                do {
                    s = atomicAdd(&g_flag[j][tile], 0);
                    if (s == 0) __nanosleep(64);
                } while (s == 0);
                s_state = s;
            }
            __syncthreads();
            const int s = s_state;
            __threadfence();
            if (s == 2) {
                const float4 hj = g_inc[j][g];
                hstart.x = fmaf(A.x, hj.x, B.x);
                hstart.y = fmaf(A.y, hj.y, B.y);
                hstart.z = fmaf(A.z, hj.z, B.z);
                hstart.w = fmaf(A.w, hj.w, B.w);
                break;
            } else {
                const float4 aj = g_pa[j][g];
                const float4 bj = g_pb[j][g];
                B.x = fmaf(A.x, bj.x, B.x);  A.x *= aj.x;
                B.y = fmaf(A.y, bj.y, B.y);  A.y *= aj.y;
                B.z = fmaf(A.z, bj.z, B.z);  A.z *= aj.z;
                B.w = fmaf(A.w, bj.w, B.w);  A.w *= aj.w;
                j--;
            }
            __syncthreads();   // protect s_state reuse
        }
    }

    // ---- Publish inclusive state (not needed for the last chunk) ----
    if (chunk < FM_NCHUNKS - 1) {
        float4 he;
        he.x = fmaf(a.x, hstart.x, b.x);
        he.y = fmaf(a.y, hstart.y, b.y);
        he.z = fmaf(a.z, hstart.z, b.z);
        he.w = fmaf(a.w, hstart.w, b.w);
        g_inc[chunk][g] = he;
        __threadfence();
        __syncthreads();
        if (tid == 0) atomicExch(&g_flag[chunk][tile], 2);
    }

    // ---- Pass B: exact recurrence from smem, streaming stores ----
    float4 h = hstart;
#pragma unroll
    for (int t = 0; t < FM_L; t++) {
        const float4 ft = sf[t * FM_TPB + tid];
        const float4 xt = sx[t * FM_TPB + tid];
        h.x = fmaf(ft.x, xt.x - h.x, h.x);
        h.y = fmaf(ft.y, xt.y - h.y, h.y);
        h.z = fmaf(ft.z, xt.z - h.z, h.z);
        h.w = fmaf(ft.w, xt.w - h.w, h.w);
        __stcs(out + base + (size_t)t * FM_NG, h);
    }
}

// ---------------- Fallback: naive per-channel scan (unexpected shapes) ----------------
__global__ void fm_naive(const float* __restrict__ f, const float* __restrict__ x,
                         const float* __restrict__ h0, float* __restrict__ out,
                         int seq, int nch)
{
    int c = blockIdx.x * blockDim.x + threadIdx.x;
    if (c >= nch) return;
    float h = h0[c];
    for (int t = 0; t < seq; t++) {
        const float ft = f[(size_t)t * nch + c];
        h = fmaf(1.f - ft, h, ft * x[(size_t)t * nch + c]);
        out[(size_t)t * nch + c] = h;
    }
}

extern "C" void kernel_launch(void* const* d_in, const int* in_sizes, int n_in,
                              void* d_out, int out_size)
{
    const float* f  = (const float*)d_in[0];
    const float* x  = (const float*)d_in[1];
    const float* h0 = (const float*)d_in[2];
    float* out      = (float*)d_out;

    const int nch = in_sizes[2];
    const int seq = in_sizes[0] / nch;

    if (seq == FM_SEQ && nch == FM_NCH) {
        cudaFuncSetAttribute(fm_fused, cudaFuncAttributeMaxDynamicSharedMemorySize,
                             FM_SMEM);
        fm_init_flags<<<(FM_NBLK + 255) / 256, 256>>>();
        fm_fused<<<FM_NBLK, FM_TPB, FM_SMEM>>>(
            (const float4*)f, (const float4*)x, (const float4*)h0, (float4*)out);
    } else {
        int tpb = 128;
        fm_naive<<<(nch + tpb - 1) / tpb, tpb>>>(f, x, h0, out, seq, nch);
    }
}

// round 6
// speedup vs baseline: 5.7691x; 1.0829x over previous
#include <cuda_runtime.h>
#include <cstdint>

// ForgetMult fused single-pass chunked scan, decoupled lookback (parallel probe).
// h_t = f_t*x_t + (1-f_t)*h_{t-1}  ==  h_t = h_{t-1} + f_t*(x_t - h_{t-1})
//
// Block (chunk, tile): cp.async its chunk tile of f,x into smem once (32 KB),
// per-channel chunk summary (a = prod(1-f), b = local scan from 0), publish
// partial, parallel-probe predecessors' flags to find nearest inclusive state,
// compose partials, publish inclusive, then exact recurrence from smem -> out.

#define FM_SEQ     2048
#define FM_NCH     16384
#define FM_NG      (FM_NCH / 4)              // 4096 float4 channel-groups
#define FM_L       8                         // timesteps per chunk
#define FM_NCHUNKS (FM_SEQ / FM_L)           // 256
#define FM_TPB     128                       // threads/block == groups per tile
#define FM_NTILES  (FM_NG / FM_TPB)          // 32
#define FM_NBLK    (FM_NCHUNKS * FM_NTILES)  // 8192

// Scratch (allocation-free rule: __device__ globals). 3 x 16 MB + flags.
__device__ float4 g_pa[FM_NCHUNKS][FM_NG];
__device__ float4 g_pb[FM_NCHUNKS][FM_NG];
__device__ float4 g_inc[FM_NCHUNKS][FM_NG];
__device__ int    g_flag[FM_NCHUNKS][FM_NTILES];  // 0=none, 1=partial, 2=inclusive

__global__ void fm_init_flags()
{
    int i = blockIdx.x * blockDim.x + threadIdx.x;
    if (i < FM_NCHUNKS * FM_NTILES) ((int*)g_flag)[i] = 0;
}

__device__ __forceinline__ void cp_async16(void* s, const void* g)
{
    uint32_t sa = (uint32_t)__cvta_generic_to_shared(s);
    asm volatile("cp.async.cg.shared.global [%0], [%1], 16;\n" :: "r"(sa), "l"(g));
}

__global__ __launch_bounds__(FM_TPB, 6) void fm_fused(
    const float4* __restrict__ f, const float4* __restrict__ x,
    const float4* __restrict__ h0, float4* __restrict__ out)
{
    // chunk-major bids: lookback waits only on lower block IDs (deadlock-free
    // under in-order dispatch).
    const int chunk = blockIdx.x / FM_NTILES;
    const int tile  = blockIdx.x % FM_NTILES;
    const int tid   = threadIdx.x;
    const int g     = tile * FM_TPB + tid;

    __shared__ float4 sf[FM_L * FM_TPB];
    __shared__ float4 sx[FM_L * FM_TPB];
    __shared__ int    s_stop;

    const size_t base = (size_t)chunk * FM_L * FM_NG + g;

    // ---- Async-load chunk tile. Each thread reads back ONLY its own slots,
    // so wait_group alone suffices (no __syncthreads needed).
#pragma unroll
    for (int t = 0; t < FM_L; t++) {
        cp_async16(&sf[t * FM_TPB + tid], f + base + (size_t)t * FM_NG);
        cp_async16(&sx[t * FM_TPB + tid], x + base + (size_t)t * FM_NG);
    }
    asm volatile("cp.async.commit_group;\n" ::: "memory");
    asm volatile("cp.async.wait_group 0;\n" ::: "memory");

    // ---- Pass A: chunk summary per channel: a = prod(1-f), b = scan from 0.
    float4 a = make_float4(1.f, 1.f, 1.f, 1.f);
    float4 b = make_float4(0.f, 0.f, 0.f, 0.f);
#pragma unroll
    for (int t = 0; t < FM_L; t++) {
        const float4 ft = sf[t * FM_TPB + tid];
        const float4 xt = sx[t * FM_TPB + tid];
        b.x = fmaf(ft.x, xt.x - b.x, b.x);  a.x *= (1.f - ft.x);
        b.y = fmaf(ft.y, xt.y - b.y, b.y);  a.y *= (1.f - ft.y);
        b.z = fmaf(ft.z, xt.z - b.z, b.z);  a.z *= (1.f - ft.z);
        b.w = fmaf(ft.w, xt.w - b.w, b.w);  a.w *= (1.f - ft.w);
    }

    // ---- Resolve h_start.
    float4 hstart;
    if (chunk == 0) {
        hstart = __ldg(h0 + g);
    } else {
        // Publish partial summary, then flag=1.
        g_pa[chunk][g] = a;
        g_pb[chunk][g] = b;
        __threadfence();
        __syncthreads();
        if (tid == 0) atomicExch(&g_flag[chunk][tile], 1);

        // Parallel probe: thread tid watches chunk-1-tid. Spin until nonzero;
        // nearest flag==2 wins via shared atomicMax. Retry round if none seen.
        const int myj = chunk - 1 - tid;
        int stop;
        for (;;) {
            if (tid == 0) s_stop = -1;
            __syncthreads();
            if (myj >= 0) {
                int s;
                do {
                    s = *(volatile int*)&g_flag[myj][tile];
                    if (s == 0) __nanosleep(64);
                } while (s == 0);
                if (s == 2) atomicMax(&s_stop, myj);
            }
            __syncthreads();
            stop = s_stop;
            if (stop >= 0) break;
        }
        __threadfence();

        // Compose: h_start = partials(stop+1 .. chunk-1) applied to h_end(stop).
        float4 h = g_inc[stop][g];
        for (int j = stop + 1; j < chunk; j++) {
            const float4 aj = g_pa[j][g];
            const float4 bj = g_pb[j][g];
            h.x = fmaf(aj.x, h.x, bj.x);
            h.y = fmaf(aj.y, h.y, bj.y);
            h.z = fmaf(aj.z, h.z, bj.z);
            h.w = fmaf(aj.w, h.w, bj.w);
        }
        hstart = h;
    }

    // ---- Publish inclusive state ASAP (successors are waiting on it).
    if (chunk < FM_NCHUNKS - 1) {
        float4 he;
        he.x = fmaf(a.x, hstart.x, b.x);
        he.y = fmaf(a.y, hstart.y, b.y);
        he.z = fmaf(a.z, hstart.z, b.z);
        he.w = fmaf(a.w, hstart.w, b.w);
        g_inc[chunk][g] = he;
        __threadfence();
        __syncthreads();
        if (tid == 0) atomicExch(&g_flag[chunk][tile], 2);
    }

    // ---- Pass B: exact recurrence from smem, streaming stores.
    float4 h = hstart;
#pragma unroll
    for (int t = 0; t < FM_L; t++) {
        const float4 ft = sf[t * FM_TPB + tid];
        const float4 xt = sx[t * FM_TPB + tid];
        h.x = fmaf(ft.x, xt.x - h.x, h.x);
        h.y = fmaf(ft.y, xt.y - h.y, h.y);
        h.z = fmaf(ft.z, xt.z - h.z, h.z);
        h.w = fmaf(ft.w, xt.w - h.w, h.w);
        __stcs(out + base + (size_t)t * FM_NG, h);
    }
}

// ---------------- Fallback: naive per-channel scan (unexpected shapes) ----------------
__global__ void fm_naive(const float* __restrict__ f, const float* __restrict__ x,
                         const float* __restrict__ h0, float* __restrict__ out,
                         int seq, int nch)
{
    int c = blockIdx.x * blockDim.x + threadIdx.x;
    if (c >= nch) return;
    float h = h0[c];
    for (int t = 0; t < seq; t++) {
        const float ft = f[(size_t)t * nch + c];
        h = fmaf(1.f - ft, h, ft * x[(size_t)t * nch + c]);
        out[(size_t)t * nch + c] = h;
    }
}

extern "C" void kernel_launch(void* const* d_in, const int* in_sizes, int n_in,
                              void* d_out, int out_size)
{
    const float* f  = (const float*)d_in[0];
    const float* x  = (const float*)d_in[1];
    const float* h0 = (const float*)d_in[2];
    float* out      = (float*)d_out;

    const int nch = in_sizes[2];
    const int seq = in_sizes[0] / nch;

    if (seq == FM_SEQ && nch == FM_NCH) {
        fm_init_flags<<<(FM_NBLK + 255) / 256, 256>>>();
        fm_fused<<<FM_NBLK, FM_TPB>>>(
            (const float4*)f, (const float4*)x, (const float4*)h0, (float4*)out);
    } else {
        int tpb = 128;
        fm_naive<<<(nch + tpb - 1) / tpb, tpb>>>(f, x, h0, out, seq, nch);
    }
}